// round 11
// baseline (speedup 1.0000x reference)
#include <cuda_runtime.h>
#include <cuda_fp16.h>
#include <cstdint>

#define B_   4
#define N_   2048
#define DIN  128
#define H_   4
#define HD_  32
#define LOG2E 1.4426950408889634f

// ---------------- scratch (no allocs allowed) ----------------
__device__ float    g_ei[B_ * N_ * H_];      // pre-scaled by log2e
__device__ float    g_ej[B_ * N_ * H_];
__device__ unsigned g_adjw[(N_ / 32) * N_];  // [jw][i]  transposed bitmask
// h f16, transposed per (b,h): [b][h][d][j]
__device__ __align__(16) unsigned short g_hp[B_ * H_ * HD_ * N_];

__device__ __forceinline__ float ex2f(float x) {
    float r; asm("ex2.approx.ftz.f32 %0, %1;" : "=f"(r) : "f"(x)); return r;
}
__device__ __forceinline__ unsigned pk_f16x2(float f0, float f1) {
    unsigned r;
    asm("cvt.rn.f16x2.f32 %0, %1, %2;" : "=r"(r) : "f"(f1), "f"(f0));
    return r;
}
__device__ __forceinline__ unsigned smem_u32(const void* p) {
    unsigned a;
    asm("{ .reg .u64 t; cvta.to.shared.u64 t, %1; cvt.u32.u64 %0, t; }" : "=r"(a) : "l"(p));
    return a;
}
#define CP16(dst, src) asm volatile("cp.async.cg.shared.global [%0], [%1], 16;" :: "r"(dst), "l"(src) : "memory")
#define CP4(dst, src)  asm volatile("cp.async.ca.shared.global [%0], [%1], 4;"  :: "r"(dst), "l"(src) : "memory")

// ---------------- kernel 1: h = x@W^T -> {f16 plane, ei, ej}; 32 rows/CTA ----------------
#define WT_STRIDE 132
#define GEMM_ROWS 32
#define GEMM_SMEM ((128 * WT_STRIDE + GEMM_ROWS * 128) * 4)
__global__ void __launch_bounds__(256, 2) k_gemm(const float* __restrict__ x,
                                                 const float* __restrict__ W,
                                                 const float* __restrict__ a) {
    extern __shared__ float sm[];
    float* Wt = sm;
    float* xs = sm + 128 * WT_STRIDE;
    const int t = threadIdx.x;
    const int row0 = blockIdx.x * GEMM_ROWS;
    for (int idx = t; idx < 128 * 128; idx += 256) {
        int c = idx >> 7, k = idx & 127;
        Wt[k * WT_STRIDE + c] = W[idx];
    }
    #pragma unroll
    for (int p = 0; p < 4; p++) {
        int idx = t + p * 256;
        *(float4*)&xs[idx * 4] = *(const float4*)&x[(size_t)row0 * 128 + idx * 4];
    }
    __syncthreads();

    const int rg = t >> 5, cg = t & 31;     // warp rg: rows rg*4..+4, lane cg: cols cg*4..+4
    float acc[4][4];
    #pragma unroll
    for (int r = 0; r < 4; r++) { acc[r][0]=acc[r][1]=acc[r][2]=acc[r][3]=0.f; }

    #pragma unroll 4
    for (int k4 = 0; k4 < 128; k4 += 4) {
        float4 wv[4];
        #pragma unroll
        for (int kk = 0; kk < 4; kk++)
            wv[kk] = *(const float4*)&Wt[(k4 + kk) * WT_STRIDE + cg * 4];
        #pragma unroll
        for (int r = 0; r < 4; r++) {
            float4 xv = *(const float4*)&xs[(rg * 4 + r) * 128 + k4];   // broadcast
            acc[r][0] = fmaf(xv.x, wv[0].x, acc[r][0]);
            acc[r][1] = fmaf(xv.x, wv[0].y, acc[r][1]);
            acc[r][2] = fmaf(xv.x, wv[0].z, acc[r][2]);
            acc[r][3] = fmaf(xv.x, wv[0].w, acc[r][3]);
            acc[r][0] = fmaf(xv.y, wv[1].x, acc[r][0]);
            acc[r][1] = fmaf(xv.y, wv[1].y, acc[r][1]);
            acc[r][2] = fmaf(xv.y, wv[1].z, acc[r][2]);
            acc[r][3] = fmaf(xv.y, wv[1].w, acc[r][3]);
            acc[r][0] = fmaf(xv.z, wv[2].x, acc[r][0]);
            acc[r][1] = fmaf(xv.z, wv[2].y, acc[r][1]);
            acc[r][2] = fmaf(xv.z, wv[2].z, acc[r][2]);
            acc[r][3] = fmaf(xv.z, wv[2].w, acc[r][3]);
            acc[r][0] = fmaf(xv.w, wv[3].x, acc[r][0]);
            acc[r][1] = fmaf(xv.w, wv[3].y, acc[r][1]);
            acc[r][2] = fmaf(xv.w, wv[3].z, acc[r][2]);
            acc[r][3] = fmaf(xv.w, wv[3].w, acc[r][3]);
        }
    }

    // ---- fused ei/ej: per-lane partial dot with a1/a2, 8-lane shuffle reduce ----
    {
        const int head = cg >> 3, din = (cg & 7) * 4;
        float a1c[4], a2c[4];
        #pragma unroll
        for (int c = 0; c < 4; c++) {
            a1c[c] = a[head * 64 + din + c] * LOG2E;
            a2c[c] = a[head * 64 + 32 + din + c] * LOG2E;
        }
        #pragma unroll
        for (int r = 0; r < 4; r++) {
            float p1 = acc[r][0]*a1c[0] + acc[r][1]*a1c[1] + acc[r][2]*a1c[2] + acc[r][3]*a1c[3];
            float p2 = acc[r][0]*a2c[0] + acc[r][1]*a2c[1] + acc[r][2]*a2c[2] + acc[r][3]*a2c[3];
            #pragma unroll
            for (int o = 1; o < 8; o <<= 1) {
                p1 += __shfl_xor_sync(0xffffffffu, p1, o, 8);
                p2 += __shfl_xor_sync(0xffffffffu, p2, o, 8);
            }
            if ((cg & 7) == 0) {
                const int row = row0 + rg * 4 + r;
                g_ei[row * H_ + head] = p1;
                g_ej[row * H_ + head] = p2;
            }
        }
    }

    // ---- transpose to f16 plane [d][j] via smem ----
    __syncthreads();
    unsigned short* sm16 = (unsigned short*)sm;    // [128 d][40]
    #pragma unroll
    for (int r = 0; r < 4; r++) {
        const int jl = rg * 4 + r;
        #pragma unroll
        for (int c = 0; c < 4; c++)
            sm16[(cg * 4 + c) * 40 + jl] = __half_as_ushort(__float2half_rn(acc[r][c]));
    }
    __syncthreads();
    {
        const int bb = row0 >> 11, j0l = row0 & 2047;
        #pragma unroll
        for (int p = 0; p < 2; p++) {
            int idx = t + p * 256;              // 0..511
            int d = idx >> 2, q = idx & 3;
            uint4 v = *(uint4*)&sm16[d * 40 + q * 8];
            int hh2 = d >> 5, dd = d & 31;
            *(uint4*)&g_hp[(((size_t)bb * H_ + hh2) * HD_ + dd) * N_ + j0l + q * 8] = v;
        }
    }
}

// ---------------- kernel 2: pack adj (8 rows/warp, 2x uint4 out) ----------------
__global__ void k_pack(const int* __restrict__ adj) {
    const int wid = threadIdx.x >> 5, lane = threadIdx.x & 31;
    const int gw = blockIdx.x * 8 + wid;           // 4096 warps
    const int ip = gw >> 4, w4 = gw & 15;          // rows 8ip..8ip+7
    const int sub = lane >> 3, idx = lane & 7;
    const size_t base = (size_t)(8 * ip) * N_ + w4 * 128 + sub * 32 + idx * 4;
    unsigned aa[8];
    #pragma unroll
    for (int k = 0; k < 8; k++) {
        int4 v = *(const int4*)&adj[base + (size_t)k * N_];
        aa[k] = ((v.x != 0 ? 1u : 0u) | (v.y != 0 ? 2u : 0u)
               | (v.z != 0 ? 4u : 0u) | (v.w != 0 ? 8u : 0u)) << (idx * 4);
    }
    #pragma unroll
    for (int o = 1; o < 8; o <<= 1)
        #pragma unroll
        for (int k = 0; k < 8; k++)
            aa[k] |= __shfl_xor_sync(0xffffffffu, aa[k], o, 8);
    if (idx == 0) {
        *(uint4*)&g_adjw[(w4 * 4 + sub) * N_ + 8 * ip]     = make_uint4(aa[0], aa[1], aa[2], aa[3]);
        *(uint4*)&g_adjw[(w4 * 4 + sub) * N_ + 8 * ip + 4] = make_uint4(aa[4], aa[5], aa[6], aa[7]);
    }
}

// ---------------- kernel 3: warp-specialized, BI=128, 512 threads, single wave ----------------
#define OFF_P0   0          // 128 x 272
#define OFF_P1   34816
#define OFF_H0   69632      // 32 x 272
#define OFF_H1   78336
#define OFF_EJ   87040      // 2 x 512B
#define OFF_ADJ  88064      // 2 x 2048B
#define OFF_ZSM  92160      // 1024B
#define OFF_ZF   93184      // 512B
#define OFF_MBAR 93696      // 4 x 8B
#define ATTN_SMEM 93728

__device__ __forceinline__ void ldsm_x4(unsigned addr, unsigned& a0, unsigned& a1,
                                        unsigned& a2, unsigned& a3) {
    asm volatile("ldmatrix.sync.aligned.m8n8.x4.shared.b16 {%0,%1,%2,%3}, [%4];"
                 : "=r"(a0), "=r"(a1), "=r"(a2), "=r"(a3) : "r"(addr));
}
__device__ __forceinline__ void mma16816(float* d, const unsigned* a, unsigned b0, unsigned b1) {
    asm volatile("mma.sync.aligned.m16n8k16.row.col.f32.f16.f16.f32 "
                 "{%0,%1,%2,%3}, {%4,%5,%6,%7}, {%8,%9}, {%0,%1,%2,%3};"
                 : "+f"(d[0]), "+f"(d[1]), "+f"(d[2]), "+f"(d[3])
                 : "r"(a[0]), "r"(a[1]), "r"(a[2]), "r"(a[3]), "r"(b0), "r"(b1));
}
__device__ __forceinline__ void mbar_wait(unsigned mb, unsigned parity) {
    asm volatile(
        "{\n\t.reg .pred P1;\n\t"
        "WL_%=:\n\t"
        "mbarrier.try_wait.parity.acquire.cta.shared::cta.b64 P1, [%0], %1, 0x989680;\n\t"
        "@P1 bra.uni WD_%=;\n\t"
        "bra.uni WL_%=;\n\t"
        "WD_%=:\n\t}"
        :: "r"(mb), "r"(parity) : "memory");
}
__device__ __forceinline__ void mbar_arrive(unsigned mb) {
    asm volatile("mbarrier.arrive.shared.b64 _, [%0];" :: "r"(mb) : "memory");
}

__global__ void __launch_bounds__(512, 2) k_attn(float* __restrict__ out) {
    extern __shared__ char smc[];
    const unsigned sb = smem_u32(smc);
    float* zsm = (float*)(smc + OFF_ZSM);
    float* zf  = (float*)(smc + OFF_ZF);

    const int t = threadIdx.x, wid = t >> 5, lane = t & 31;
    const int i0 = blockIdx.x * 128, hh = blockIdx.y, b = blockIdx.z;

    const unsigned mb_pfull0  = sb + OFF_MBAR;
    const unsigned mb_pfull1  = sb + OFF_MBAR + 8;
    const unsigned mb_pempty0 = sb + OFF_MBAR + 16;
    const unsigned mb_pempty1 = sb + OFF_MBAR + 24;

    if (t == 0) {
        asm volatile("mbarrier.init.shared.b64 [%0], %1;" :: "r"(mb_pfull0),  "r"(256u) : "memory");
        asm volatile("mbarrier.init.shared.b64 [%0], %1;" :: "r"(mb_pfull1),  "r"(256u) : "memory");
        asm volatile("mbarrier.init.shared.b64 [%0], %1;" :: "r"(mb_pempty0), "r"(256u) : "memory");
        asm volatile("mbarrier.init.shared.b64 [%0], %1;" :: "r"(mb_pempty1), "r"(256u) : "memory");
    }
    __syncthreads();

    if (wid < 8) {
        // ================= PRODUCERS (t in [0,256)) =================
        const int iA = t >> 1, jq2 = t & 1;
        const float ei_r = g_ei[(b * N_ + i0 + iA) * H_ + hh];
        float zpart = 0.f;
        const unsigned short* hp = g_hp + ((size_t)((b * H_ + hh) * HD_)) * N_;

        #define ISSUE_COPIES(tl, buf)                                                       \
        do {                                                                                \
            const int jj0 = (tl) * 128;                                                     \
            const unsigned offH_ = (buf) ? OFF_H1 : OFF_H0;                                 \
            _Pragma("unroll")                                                               \
            for (int r = 0; r < 2; r++) {                                                   \
                int id = t + r * 256;                                                       \
                int d = id >> 4, q = id & 15;                                               \
                CP16(sb + offH_ + d * 272 + q * 16, &hp[(size_t)d * N_ + jj0 + q * 8]);     \
            }                                                                               \
            if (t < 128)                                                                    \
                CP4(sb + OFF_EJ + (buf) * 512 + t * 4, &g_ej[(b * N_ + jj0 + t) * H_ + hh]); \
            if (t < 128) {                                                                  \
                int jwl = t >> 5, il4 = (t & 31) * 4;                                       \
                CP16(sb + OFF_ADJ + (buf) * 2048 + (jwl * 128 + il4) * 4,                   \
                     &g_adjw[((jj0 >> 5) + jwl) * N_ + i0 + il4]);                          \
            }                                                                               \
            asm volatile("cp.async.commit_group;" ::: "memory");                            \
        } while (0)

        ISSUE_COPIES(0, 0);

        for (int tile = 0; tile < 16; tile++) {
            const int cur = tile & 1;

            if (tile + 1 < 16) {
                if (tile + 1 >= 2)
                    mbar_wait((tile & 1) ? mb_pempty0 : mb_pempty1,
                              (unsigned)((((tile + 1) >> 1) - 1) & 1));
                ISSUE_COPIES(tile + 1, (tile + 1) & 1);
                asm volatile("cp.async.wait_group 1;" ::: "memory");
            } else {
                asm volatile("cp.async.wait_group 0;" ::: "memory");
            }
            asm volatile("bar.sync 1, 256;" ::: "memory");

            // scores: 64 j per thread
            {
                const unsigned* aw = (const unsigned*)(smc + OFF_ADJ + cur * 2048);
                const unsigned w0 = aw[(jq2 * 2 + 0) * 128 + iA];
                const unsigned w1 = aw[(jq2 * 2 + 1) * 128 + iA];
                const float* ejq = (const float*)(smc + OFF_EJ + cur * 512) + jq2 * 64;
                char* phiRow = smc + (cur ? OFF_P1 : OFF_P0) + iA * 272 + jq2 * 128;
                #pragma unroll 8
                for (int q = 0; q < 16; q++) {
                    const unsigned w = (q < 8) ? w0 : w1;
                    const int bit = (q & 7) * 4;
                    float4 ev = *(const float4*)&ejq[q * 4];
                    float s0 = ei_r + ev.x, s1 = ei_r + ev.y;
                    float s2 = ei_r + ev.z, s3 = ei_r + ev.w;
                    s0 = fmaxf(s0, 0.2f * s0); s1 = fmaxf(s1, 0.2f * s1);
                    s2 = fmaxf(s2, 0.2f * s2); s3 = fmaxf(s3, 0.2f * s3);
                    float e0 = ex2f(s0), e1 = ex2f(s1), e2 = ex2f(s2), e3 = ex2f(s3);
                    e0 = ((w >> (bit + 0)) & 1u) ? e0 : 0.f;
                    e1 = ((w >> (bit + 1)) & 1u) ? e1 : 0.f;
                    e2 = ((w >> (bit + 2)) & 1u) ? e2 : 0.f;
                    e3 = ((w >> (bit + 3)) & 1u) ? e3 : 0.f;
                    zpart += (e0 + e1) + (e2 + e3);
                    *(uint2*)(phiRow + q * 8) = make_uint2(pk_f16x2(e0, e1), pk_f16x2(e2, e3));
                }
            }
            mbar_arrive(cur ? mb_pfull1 : mb_pfull0);
        }

        zsm[jq2 * 128 + iA] = zpart;
        asm volatile("bar.sync 1, 256;" ::: "memory");
        if (t < 128) zf[t] = 1.0f / (zsm[t] + zsm[128 + t]);
        __syncthreads();       // join with consumers
    } else {
        // ================= CONSUMERS (warps 8-15) =================
        const int w = wid - 8;
        const unsigned aAr = (unsigned)(w * 16 + (lane & 15)) * 272u + ((lane >> 4) & 1) * 16u;
        const unsigned bRow = (unsigned)((lane & 7) + ((lane >> 4) & 1) * 8) * 272u
                            + ((lane >> 3) & 1) * 16u;
        float dacc[4][4];
        #pragma unroll
        for (int nb = 0; nb < 4; nb++)
            #pragma unroll
            for (int k = 0; k < 4; k++) dacc[nb][k] = 0.f;

        for (int tile = 0; tile < 16; tile++) {
            const int cur = tile & 1;
            mbar_wait(cur ? mb_pfull1 : mb_pfull0, (unsigned)((tile >> 1) & 1));
            const unsigned aA  = sb + (cur ? OFF_P1 : OFF_P0) + aAr;
            const unsigned aB0 = sb + (cur ? OFF_H1 : OFF_H0) + bRow;
            const unsigned aB1 = aB0 + 16u * 272u;
            #pragma unroll
            for (int ks = 0; ks < 8; ks++) {
                const unsigned off = (unsigned)ks * 32u;
                unsigned a[4], b0, b1, c0, c1, e0, e1, f0, f1;
                ldsm_x4(aA + off, a[0], a[1], a[2], a[3]);
                ldsm_x4(aB0 + off, b0, b1, c0, c1);
                ldsm_x4(aB1 + off, e0, e1, f0, f1);
                mma16816(dacc[0], a, b0, b1);
                mma16816(dacc[1], a, c0, c1);
                mma16816(dacc[2], a, e0, e1);
                mma16816(dacc[3], a, f0, f1);
            }
            mbar_arrive(cur ? mb_pempty1 : mb_pempty0);
        }

        __syncthreads();       // join: zf ready

        const int gid = lane >> 2, tig = lane & 3;
        const float zi0 = zf[w * 16 + gid], zi1 = zf[w * 16 + gid + 8];
        const size_t r0 = (size_t)(b * N_) + i0 + w * 16 + gid;
        float* o0 = out + r0 * DIN + hh * HD_ + 2 * tig;
        float* o1 = o0 + 8 * DIN;
        #pragma unroll
        for (int nb = 0; nb < 4; nb++) {
            *(float2*)(o0 + nb * 8) = make_float2(dacc[nb][0] * zi0, dacc[nb][1] * zi0);
            *(float2*)(o1 + nb * 8) = make_float2(dacc[nb][2] * zi1, dacc[nb][3] * zi1);
        }
    }
}

// ---------------- launch ----------------
extern "C" void kernel_launch(void* const* d_in, const int* in_sizes, int n_in,
                              void* d_out, int out_size) {
    const float* x   = (const float*)d_in[0];
    const int*   adj = (const int*)d_in[1];
    const float* W   = (const float*)d_in[2];
    const float* a   = (const float*)d_in[3];
    float*       out = (float*)d_out;

    cudaFuncSetAttribute(k_gemm, cudaFuncAttributeMaxDynamicSharedMemorySize, GEMM_SMEM);
    cudaFuncSetAttribute(k_attn, cudaFuncAttributeMaxDynamicSharedMemorySize, ATTN_SMEM);

    k_gemm<<<B_ * N_ / GEMM_ROWS, 256, GEMM_SMEM>>>(x, W, a);
    k_pack<<<512, 256>>>(adj);
    k_attn<<<dim3(N_ / 128, H_, B_), 512, ATTN_SMEM>>>(out);
}

// round 12
// speedup vs baseline: 1.0583x; 1.0583x over previous
#include <cuda_runtime.h>
#include <cuda_fp16.h>
#include <cstdint>

#define B_   4
#define N_   2048
#define DIN  128
#define H_   4
#define HD_  32
#define LOG2E 1.4426950408889634f

// ---------------- scratch (no allocs allowed) ----------------
__device__ float    g_ei[B_ * N_ * H_];      // pre-scaled by log2e
__device__ float    g_ej[B_ * N_ * H_];
__device__ unsigned g_adjw[(N_ / 32) * N_];  // [jw][i]  transposed bitmask
__device__ __align__(16) unsigned short g_hp[B_ * H_ * HD_ * N_];   // h f16 [b][h][d][j]
__device__ __align__(16) unsigned short g_w16hi[DIN * DIN];         // W split f16
__device__ __align__(16) unsigned short g_w16lo[DIN * DIN];

__device__ __forceinline__ float ex2f(float x) {
    float r; asm("ex2.approx.ftz.f32 %0, %1;" : "=f"(r) : "f"(x)); return r;
}
__device__ __forceinline__ unsigned pk_f16x2(float f0, float f1) {
    unsigned r;
    asm("cvt.rn.f16x2.f32 %0, %1, %2;" : "=r"(r) : "f"(f1), "f"(f0));
    return r;
}
__device__ __forceinline__ void unpk_f16x2(unsigned u, float& f0, float& f1) {
    asm("{ .reg .f16 l, h; mov.b32 {l, h}, %2; cvt.f32.f16 %0, l; cvt.f32.f16 %1, h; }"
        : "=f"(f0), "=f"(f1) : "r"(u));
}
__device__ __forceinline__ unsigned smem_u32(const void* p) {
    unsigned a;
    asm("{ .reg .u64 t; cvta.to.shared.u64 t, %1; cvt.u32.u64 %0, t; }" : "=r"(a) : "l"(p));
    return a;
}
#define CP16(dst, src) asm volatile("cp.async.cg.shared.global [%0], [%1], 16;" :: "r"(dst), "l"(src) : "memory")
#define CP4(dst, src)  asm volatile("cp.async.ca.shared.global [%0], [%1], 4;"  :: "r"(dst), "l"(src) : "memory")

__device__ __forceinline__ void ldsm_x4(unsigned addr, unsigned& a0, unsigned& a1,
                                        unsigned& a2, unsigned& a3) {
    asm volatile("ldmatrix.sync.aligned.m8n8.x4.shared.b16 {%0,%1,%2,%3}, [%4];"
                 : "=r"(a0), "=r"(a1), "=r"(a2), "=r"(a3) : "r"(addr));
}
__device__ __forceinline__ void mma16816(float* d, const unsigned* a, unsigned b0, unsigned b1) {
    asm volatile("mma.sync.aligned.m16n8k16.row.col.f32.f16.f16.f32 "
                 "{%0,%1,%2,%3}, {%4,%5,%6,%7}, {%8,%9}, {%0,%1,%2,%3};"
                 : "+f"(d[0]), "+f"(d[1]), "+f"(d[2]), "+f"(d[3])
                 : "r"(a[0]), "r"(a[1]), "r"(a[2]), "r"(a[3]), "r"(b0), "r"(b1));
}
__device__ __forceinline__ void mbar_wait(unsigned mb, unsigned parity) {
    asm volatile(
        "{\n\t.reg .pred P1;\n\t"
        "WL_%=:\n\t"
        "mbarrier.try_wait.parity.acquire.cta.shared::cta.b64 P1, [%0], %1, 0x989680;\n\t"
        "@P1 bra.uni WD_%=;\n\t"
        "bra.uni WL_%=;\n\t"
        "WD_%=:\n\t}"
        :: "r"(mb), "r"(parity) : "memory");
}
__device__ __forceinline__ void mbar_arrive(unsigned mb) {
    asm volatile("mbarrier.arrive.shared.b64 _, [%0];" :: "r"(mb) : "memory");
}

// ---------------- kernel 0: split W -> f16 hi/lo planes ----------------
__global__ void k_prep(const float* __restrict__ W) {
    const int idx = (blockIdx.x * 256 + threadIdx.x) * 8;
    float4 v0 = *(const float4*)&W[idx];
    float4 v1 = *(const float4*)&W[idx + 4];
    float f[8] = {v0.x, v0.y, v0.z, v0.w, v1.x, v1.y, v1.z, v1.w};
    unsigned hi[4], lo[4];
    #pragma unroll
    for (int p = 0; p < 4; p++) {
        unsigned uh = pk_f16x2(f[2*p], f[2*p+1]);
        float g0, g1; unpk_f16x2(uh, g0, g1);
        hi[p] = uh;
        lo[p] = pk_f16x2(f[2*p] - g0, f[2*p+1] - g1);
    }
    *(uint4*)&g_w16hi[idx] = make_uint4(hi[0], hi[1], hi[2], hi[3]);
    *(uint4*)&g_w16lo[idx] = make_uint4(lo[0], lo[1], lo[2], lo[3]);
}

// ---------------- kernel 1: h = x@W^T via split-f16 HMMA; 32 rows/CTA ----------------
// smem: XHI [32][136h], XLO, WHI [128][136h], WLO; epilogue f32 [32][136] reuses X area
#define GX_HI 0
#define GX_LO 8704
#define GW_HI 17408
#define GW_LO 52224
#define GEMM_SMEM 87040
__global__ void __launch_bounds__(256, 2) k_gemm(const float* __restrict__ x,
                                                 const float* __restrict__ a) {
    extern __shared__ char smg[];
    const unsigned sb = smem_u32(smg);
    const int t = threadIdx.x, wid = t >> 5, lane = t & 31;
    const int row0 = blockIdx.x * 32;

    // stage W hi/lo via cp.async (16 CP16/thread, L2-resident source)
    #pragma unroll
    for (int r = 0; r < 8; r++) {
        int id = t + r * 256;
        int d = id >> 4, q = id & 15;
        CP16(sb + GW_HI + d * 272 + q * 16, &g_w16hi[d * 128 + q * 8]);
        CP16(sb + GW_LO + d * 272 + q * 16, &g_w16lo[d * 128 + q * 8]);
    }
    asm volatile("cp.async.commit_group;" ::: "memory");

    // stage x: convert 16 fp32 -> f16 hi/lo
    {
        const int row = t >> 3, cq = (t & 7) * 16;
        const float* src = &x[(size_t)(row0 + row) * 128 + cq];
        float f[16];
        #pragma unroll
        for (int p = 0; p < 4; p++) {
            float4 v = *(const float4*)&src[p * 4];
            f[4*p] = v.x; f[4*p+1] = v.y; f[4*p+2] = v.z; f[4*p+3] = v.w;
        }
        unsigned hi[8], lo[8];
        #pragma unroll
        for (int p = 0; p < 8; p++) {
            unsigned uh = pk_f16x2(f[2*p], f[2*p+1]);
            float g0, g1; unpk_f16x2(uh, g0, g1);
            hi[p] = uh;
            lo[p] = pk_f16x2(f[2*p] - g0, f[2*p+1] - g1);
        }
        char* dh = smg + GX_HI + row * 272 + cq * 2;
        char* dl = smg + GX_LO + row * 272 + cq * 2;
        *(uint4*)dh       = make_uint4(hi[0], hi[1], hi[2], hi[3]);
        *(uint4*)(dh+16)  = make_uint4(hi[4], hi[5], hi[6], hi[7]);
        *(uint4*)dl       = make_uint4(lo[0], lo[1], lo[2], lo[3]);
        *(uint4*)(dl+16)  = make_uint4(lo[4], lo[5], lo[6], lo[7]);
    }
    asm volatile("cp.async.wait_group 0;" ::: "memory");
    __syncthreads();

    // MMA: warp w -> n strip w*16, m = 32 (2 tiles)
    const int n0 = wid * 16;
    const unsigned aAh0 = sb + GX_HI + (unsigned)(lane & 15) * 272u + ((lane >> 4) & 1) * 16u;
    const unsigned aAh1 = aAh0 + 16u * 272u;
    const unsigned aAl0 = aAh0 + (GX_LO - GX_HI);
    const unsigned aAl1 = aAh1 + (GX_LO - GX_HI);
    const unsigned bB   = sb + GW_HI + (unsigned)(n0 + (lane & 7) + ((lane >> 4) & 1) * 8) * 272u
                        + ((lane >> 3) & 1) * 16u;
    const unsigned bBl  = bB + (GW_LO - GW_HI);

    float acc[2][2][4];
    #pragma unroll
    for (int mt = 0; mt < 2; mt++)
        #pragma unroll
        for (int nt = 0; nt < 2; nt++)
            #pragma unroll
            for (int k = 0; k < 4; k++) acc[mt][nt][k] = 0.f;

    #pragma unroll
    for (int ks = 0; ks < 8; ks++) {
        const unsigned off = (unsigned)ks * 32u;
        unsigned ah0[4], ah1[4], al0[4], al1[4];
        unsigned bh0, bh1, ch0, ch1, bl0, bl1, cl0, cl1;
        ldsm_x4(aAh0 + off, ah0[0], ah0[1], ah0[2], ah0[3]);
        ldsm_x4(aAh1 + off, ah1[0], ah1[1], ah1[2], ah1[3]);
        ldsm_x4(aAl0 + off, al0[0], al0[1], al0[2], al0[3]);
        ldsm_x4(aAl1 + off, al1[0], al1[1], al1[2], al1[3]);
        ldsm_x4(bB  + off, bh0, bh1, ch0, ch1);
        ldsm_x4(bBl + off, bl0, bl1, cl0, cl1);
        mma16816(acc[0][0], ah0, bh0, bh1);
        mma16816(acc[0][0], ah0, bl0, bl1);
        mma16816(acc[0][0], al0, bh0, bh1);
        mma16816(acc[0][1], ah0, ch0, ch1);
        mma16816(acc[0][1], ah0, cl0, cl1);
        mma16816(acc[0][1], al0, ch0, ch1);
        mma16816(acc[1][0], ah1, bh0, bh1);
        mma16816(acc[1][0], ah1, bl0, bl1);
        mma16816(acc[1][0], al1, bh0, bh1);
        mma16816(acc[1][1], ah1, ch0, ch1);
        mma16816(acc[1][1], ah1, cl0, cl1);
        mma16816(acc[1][1], al1, ch0, ch1);
    }

    // epilogue: park fp32 h tile in smem [32][136]
    __syncthreads();
    float* sm32 = (float*)smg;
    #pragma unroll
    for (int mt = 0; mt < 2; mt++)
        #pragma unroll
        for (int nt = 0; nt < 2; nt++) {
            const int r = mt * 16 + (lane >> 2);
            const int c = n0 + nt * 8 + 2 * (lane & 3);
            *(float2*)&sm32[r * 136 + c]       = make_float2(acc[mt][nt][0], acc[mt][nt][1]);
            *(float2*)&sm32[(r + 8) * 136 + c] = make_float2(acc[mt][nt][2], acc[mt][nt][3]);
        }
    __syncthreads();

    // f16 plane [d][j]
    {
        const int bb = row0 >> 11, j0l = row0 & 2047;
        const int d = t >> 1, jh = t & 1;
        unsigned u[8];
        #pragma unroll
        for (int p = 0; p < 8; p++)
            u[p] = pk_f16x2(sm32[(jh * 16 + 2*p) * 136 + d], sm32[(jh * 16 + 2*p + 1) * 136 + d]);
        unsigned short* dst = &g_hp[(((size_t)bb * H_ + (d >> 5)) * HD_ + (d & 31)) * N_ + j0l + jh * 16];
        *(uint4*)dst      = make_uint4(u[0], u[1], u[2], u[3]);
        *(uint4*)(dst+8)  = make_uint4(u[4], u[5], u[6], u[7]);
    }

    // ei/ej: thread -> (row, head, half16)
    {
        const int r = t >> 3, q = t & 7;
        const int head = q >> 1, part = q & 1;
        const float* hrow = &sm32[r * 136 + head * 32 + part * 16];
        const float* a1 = &a[head * 64 + part * 16];
        const float* a2 = a1 + 32;
        float p1 = 0.f, p2 = 0.f;
        #pragma unroll
        for (int dd = 0; dd < 16; dd++) {
            float hv = hrow[dd];
            p1 = fmaf(hv, a1[dd], p1);
            p2 = fmaf(hv, a2[dd], p2);
        }
        p1 += __shfl_xor_sync(0xffffffffu, p1, 1);
        p2 += __shfl_xor_sync(0xffffffffu, p2, 1);
        if (part == 0) {
            const int row = row0 + r;
            g_ei[row * H_ + head] = p1 * LOG2E;
            g_ej[row * H_ + head] = p2 * LOG2E;
        }
    }
}

// ---------------- kernel 2: pack adj (8 rows/warp, 2x uint4 out) ----------------
__global__ void k_pack(const int* __restrict__ adj) {
    const int wid = threadIdx.x >> 5, lane = threadIdx.x & 31;
    const int gw = blockIdx.x * 8 + wid;
    const int ip = gw >> 4, w4 = gw & 15;
    const int sub = lane >> 3, idx = lane & 7;
    const size_t base = (size_t)(8 * ip) * N_ + w4 * 128 + sub * 32 + idx * 4;
    unsigned aa[8];
    #pragma unroll
    for (int k = 0; k < 8; k++) {
        int4 v = *(const int4*)&adj[base + (size_t)k * N_];
        aa[k] = ((v.x != 0 ? 1u : 0u) | (v.y != 0 ? 2u : 0u)
               | (v.z != 0 ? 4u : 0u) | (v.w != 0 ? 8u : 0u)) << (idx * 4);
    }
    #pragma unroll
    for (int o = 1; o < 8; o <<= 1)
        #pragma unroll
        for (int k = 0; k < 8; k++)
            aa[k] |= __shfl_xor_sync(0xffffffffu, aa[k], o, 8);
    if (idx == 0) {
        *(uint4*)&g_adjw[(w4 * 4 + sub) * N_ + 8 * ip]     = make_uint4(aa[0], aa[1], aa[2], aa[3]);
        *(uint4*)&g_adjw[(w4 * 4 + sub) * N_ + 8 * ip + 4] = make_uint4(aa[4], aa[5], aa[6], aa[7]);
    }
}

// ---------------- kernel 3: warp-specialized, BI=128, 512 threads, single wave ----------------
#define OFF_P0   0
#define OFF_P1   34816
#define OFF_H0   69632
#define OFF_H1   78336
#define OFF_EJ   87040
#define OFF_ADJ  88064
#define OFF_ZSM  92160
#define OFF_ZF   93184
#define OFF_MBAR 93696
#define ATTN_SMEM 93728

__global__ void __launch_bounds__(512, 2) k_attn(float* __restrict__ out) {
    extern __shared__ char smc[];
    const unsigned sb = smem_u32(smc);
    float* zsm = (float*)(smc + OFF_ZSM);
    float* zf  = (float*)(smc + OFF_ZF);

    const int t = threadIdx.x, wid = t >> 5, lane = t & 31;
    const int i0 = blockIdx.x * 128, hh = blockIdx.y, b = blockIdx.z;

    const unsigned mb_pfull0  = sb + OFF_MBAR;
    const unsigned mb_pfull1  = sb + OFF_MBAR + 8;
    const unsigned mb_pempty0 = sb + OFF_MBAR + 16;
    const unsigned mb_pempty1 = sb + OFF_MBAR + 24;

    if (t == 0) {
        asm volatile("mbarrier.init.shared.b64 [%0], %1;" :: "r"(mb_pfull0),  "r"(256u) : "memory");
        asm volatile("mbarrier.init.shared.b64 [%0], %1;" :: "r"(mb_pfull1),  "r"(256u) : "memory");
        asm volatile("mbarrier.init.shared.b64 [%0], %1;" :: "r"(mb_pempty0), "r"(256u) : "memory");
        asm volatile("mbarrier.init.shared.b64 [%0], %1;" :: "r"(mb_pempty1), "r"(256u) : "memory");
    }
    __syncthreads();

    if (wid < 8) {
        // ================= PRODUCERS (t in [0,256)) =================
        const int iA = t >> 1, jq2 = t & 1;
        const float ei_r = g_ei[(b * N_ + i0 + iA) * H_ + hh];
        float zpart = 0.f;
        const unsigned short* hp = g_hp + ((size_t)((b * H_ + hh) * HD_)) * N_;

        #define ISSUE_COPIES(tl, buf)                                                       \
        do {                                                                                \
            const int jj0 = (tl) * 128;                                                     \
            const unsigned offH_ = (buf) ? OFF_H1 : OFF_H0;                                 \
            _Pragma("unroll")                                                               \
            for (int r = 0; r < 2; r++) {                                                   \
                int id = t + r * 256;                                                       \
                int d = id >> 4, q = id & 15;                                               \
                CP16(sb + offH_ + d * 272 + q * 16, &hp[(size_t)d * N_ + jj0 + q * 8]);     \
            }                                                                               \
            if (t < 128)                                                                    \
                CP4(sb + OFF_EJ + (buf) * 512 + t * 4, &g_ej[(b * N_ + jj0 + t) * H_ + hh]); \
            if (t < 128) {                                                                  \
                int jwl = t >> 5, il4 = (t & 31) * 4;                                       \
                CP16(sb + OFF_ADJ + (buf) * 2048 + (jwl * 128 + il4) * 4,                   \
                     &g_adjw[((jj0 >> 5) + jwl) * N_ + i0 + il4]);                          \
            }                                                                               \
            asm volatile("cp.async.commit_group;" ::: "memory");                            \
        } while (0)

        ISSUE_COPIES(0, 0);

        for (int tile = 0; tile < 16; tile++) {
            const int cur = tile & 1;

            if (tile + 1 < 16) {
                if (tile + 1 >= 2)
                    mbar_wait((tile & 1) ? mb_pempty0 : mb_pempty1,
                              (unsigned)((((tile + 1) >> 1) - 1) & 1));
                ISSUE_COPIES(tile + 1, (tile + 1) & 1);
                asm volatile("cp.async.wait_group 1;" ::: "memory");
            } else {
                asm volatile("cp.async.wait_group 0;" ::: "memory");
            }
            asm volatile("bar.sync 1, 256;" ::: "memory");

            {
                const unsigned* aw = (const unsigned*)(smc + OFF_ADJ + cur * 2048);
                const unsigned w0 = aw[(jq2 * 2 + 0) * 128 + iA];
                const unsigned w1 = aw[(jq2 * 2 + 1) * 128 + iA];
                const float* ejq = (const float*)(smc + OFF_EJ + cur * 512) + jq2 * 64;
                char* phiRow = smc + (cur ? OFF_P1 : OFF_P0) + iA * 272 + jq2 * 128;
                #pragma unroll 8
                for (int q = 0; q < 16; q++) {
                    const unsigned w = (q < 8) ? w0 : w1;
                    const int bit = (q & 7) * 4;
                    float4 ev = *(const float4*)&ejq[q * 4];
                    float s0 = ei_r + ev.x, s1 = ei_r + ev.y;
                    float s2 = ei_r + ev.z, s3 = ei_r + ev.w;
                    s0 = fmaxf(s0, 0.2f * s0); s1 = fmaxf(s1, 0.2f * s1);
                    s2 = fmaxf(s2, 0.2f * s2); s3 = fmaxf(s3, 0.2f * s3);
                    float e0 = ex2f(s0), e1 = ex2f(s1), e2 = ex2f(s2), e3 = ex2f(s3);
                    e0 = ((w >> (bit + 0)) & 1u) ? e0 : 0.f;
                    e1 = ((w >> (bit + 1)) & 1u) ? e1 : 0.f;
                    e2 = ((w >> (bit + 2)) & 1u) ? e2 : 0.f;
                    e3 = ((w >> (bit + 3)) & 1u) ? e3 : 0.f;
                    zpart += (e0 + e1) + (e2 + e3);
                    *(uint2*)(phiRow + q * 8) = make_uint2(pk_f16x2(e0, e1), pk_f16x2(e2, e3));
                }
            }
            mbar_arrive(cur ? mb_pfull1 : mb_pfull0);
        }

        zsm[jq2 * 128 + iA] = zpart;
        asm volatile("bar.sync 1, 256;" ::: "memory");
        if (t < 128) zf[t] = 1.0f / (zsm[t] + zsm[128 + t]);
        __syncthreads();
    } else {
        // ================= CONSUMERS (warps 8-15) =================
        const int w = wid - 8;
        const unsigned aAr = (unsigned)(w * 16 + (lane & 15)) * 272u + ((lane >> 4) & 1) * 16u;
        const unsigned bRow = (unsigned)((lane & 7) + ((lane >> 4) & 1) * 8) * 272u
                            + ((lane >> 3) & 1) * 16u;
        float dacc[4][4];
        #pragma unroll
        for (int nb = 0; nb < 4; nb++)
            #pragma unroll
            for (int k = 0; k < 4; k++) dacc[nb][k] = 0.f;

        for (int tile = 0; tile < 16; tile++) {
            const int cur = tile & 1;
            mbar_wait(cur ? mb_pfull1 : mb_pfull0, (unsigned)((tile >> 1) & 1));
            const unsigned aA  = sb + (cur ? OFF_P1 : OFF_P0) + aAr;
            const unsigned aB0 = sb + (cur ? OFF_H1 : OFF_H0) + bRow;
            const unsigned aB1 = aB0 + 16u * 272u;
            #pragma unroll
            for (int ks = 0; ks < 8; ks++) {
                const unsigned off = (unsigned)ks * 32u;
                unsigned a[4], b0, b1, c0, c1, e0, e1, f0, f1;
                ldsm_x4(aA + off, a[0], a[1], a[2], a[3]);
                ldsm_x4(aB0 + off, b0, b1, c0, c1);
                ldsm_x4(aB1 + off, e0, e1, f0, f1);
                mma16816(dacc[0], a, b0, b1);
                mma16816(dacc[1], a, c0, c1);
                mma16816(dacc[2], a, e0, e1);
                mma16816(dacc[3], a, f0, f1);
            }
            mbar_arrive(cur ? mb_pempty1 : mb_pempty0);
        }

        __syncthreads();

        const int gid = lane >> 2, tig = lane & 3;
        const float zi0 = zf[w * 16 + gid], zi1 = zf[w * 16 + gid + 8];
        const size_t r0 = (size_t)(b * N_) + i0 + w * 16 + gid;
        float* o0 = out + r0 * DIN + hh * HD_ + 2 * tig;
        float* o1 = o0 + 8 * DIN;
        #pragma unroll
        for (int nb = 0; nb < 4; nb++) {
            *(float2*)(o0 + nb * 8) = make_float2(dacc[nb][0] * zi0, dacc[nb][1] * zi0);
            *(float2*)(o1 + nb * 8) = make_float2(dacc[nb][2] * zi1, dacc[nb][3] * zi1);
        }
    }
}

// ---------------- launch ----------------
extern "C" void kernel_launch(void* const* d_in, const int* in_sizes, int n_in,
                              void* d_out, int out_size) {
    const float* x   = (const float*)d_in[0];
    const int*   adj = (const int*)d_in[1];
    const float* W   = (const float*)d_in[2];
    const float* a   = (const float*)d_in[3];
    float*       out = (float*)d_out;

    cudaFuncSetAttribute(k_gemm, cudaFuncAttributeMaxDynamicSharedMemorySize, GEMM_SMEM);
    cudaFuncSetAttribute(k_attn, cudaFuncAttributeMaxDynamicSharedMemorySize, ATTN_SMEM);

    k_prep<<<8, 256>>>(W);
    k_gemm<<<B_ * N_ / 32, 256, GEMM_SMEM>>>(x, a);
    k_pack<<<512, 256>>>(adj);
    k_attn<<<dim3(N_ / 128, H_, B_), 512, ATTN_SMEM>>>(out);
}

// round 14
// speedup vs baseline: 1.2565x; 1.1874x over previous
#include <cuda_runtime.h>
#include <cuda_fp16.h>
#include <cstdint>

#define B_   4
#define N_   2048
#define DIN  128
#define H_   4
#define HD_  32
#define LOG2E 1.4426950408889634f

// ---------------- scratch (no allocs allowed) ----------------
__device__ float    g_ei[B_ * N_ * H_];      // pre-scaled by log2e
__device__ float    g_ej[B_ * N_ * H_];
__device__ unsigned g_adjw[(N_ / 32) * N_];  // [jw][i]  transposed bitmask
__device__ __align__(16) unsigned short g_hp[B_ * H_ * HD_ * N_];   // h f16 [b][h][d][j]
__device__ __align__(16) unsigned short g_w16hi[DIN * DIN];         // W split f16
__device__ __align__(16) unsigned short g_w16lo[DIN * DIN];

__device__ __forceinline__ float ex2f(float x) {
    float r; asm("ex2.approx.ftz.f32 %0, %1;" : "=f"(r) : "f"(x)); return r;
}
__device__ __forceinline__ unsigned pk_f16x2(float f0, float f1) {
    unsigned r;
    asm("cvt.rn.f16x2.f32 %0, %1, %2;" : "=r"(r) : "f"(f1), "f"(f0));
    return r;
}
__device__ __forceinline__ void unpk_f16x2(unsigned u, float& f0, float& f1) {
    asm("{ .reg .f16 l, h; mov.b32 {l, h}, %2; cvt.f32.f16 %0, l; cvt.f32.f16 %1, h; }"
        : "=f"(f0), "=f"(f1) : "r"(u));
}
__device__ __forceinline__ unsigned smem_u32(const void* p) {
    unsigned a;
    asm("{ .reg .u64 t; cvta.to.shared.u64 t, %1; cvt.u32.u64 %0, t; }" : "=r"(a) : "l"(p));
    return a;
}
#define CP16(dst, src) asm volatile("cp.async.cg.shared.global [%0], [%1], 16;" :: "r"(dst), "l"(src) : "memory")
#define CP4(dst, src)  asm volatile("cp.async.ca.shared.global [%0], [%1], 4;"  :: "r"(dst), "l"(src) : "memory")

__device__ __forceinline__ void ldsm_x4(unsigned addr, unsigned& a0, unsigned& a1,
                                        unsigned& a2, unsigned& a3) {
    asm volatile("ldmatrix.sync.aligned.m8n8.x4.shared.b16 {%0,%1,%2,%3}, [%4];"
                 : "=r"(a0), "=r"(a1), "=r"(a2), "=r"(a3) : "r"(addr));
}
__device__ __forceinline__ void mma16816(float* d, const unsigned* a, unsigned b0, unsigned b1) {
    asm volatile("mma.sync.aligned.m16n8k16.row.col.f32.f16.f16.f32 "
                 "{%0,%1,%2,%3}, {%4,%5,%6,%7}, {%8,%9}, {%0,%1,%2,%3};"
                 : "+f"(d[0]), "+f"(d[1]), "+f"(d[2]), "+f"(d[3])
                 : "r"(a[0]), "r"(a[1]), "r"(a[2]), "r"(a[3]), "r"(b0), "r"(b1));
}

// ---------------- kernel 0: split W -> f16 hi/lo planes ----------------
__global__ void k_prep(const float* __restrict__ W) {
    const int idx = (blockIdx.x * 256 + threadIdx.x) * 8;
    float4 v0 = *(const float4*)&W[idx];
    float4 v1 = *(const float4*)&W[idx + 4];
    float f[8] = {v0.x, v0.y, v0.z, v0.w, v1.x, v1.y, v1.z, v1.w};
    unsigned hi[4], lo[4];
    #pragma unroll
    for (int p = 0; p < 4; p++) {
        unsigned uh = pk_f16x2(f[2*p], f[2*p+1]);
        float g0, g1; unpk_f16x2(uh, g0, g1);
        hi[p] = uh;
        lo[p] = pk_f16x2(f[2*p] - g0, f[2*p+1] - g1);
    }
    *(uint4*)&g_w16hi[idx] = make_uint4(hi[0], hi[1], hi[2], hi[3]);
    *(uint4*)&g_w16lo[idx] = make_uint4(lo[0], lo[1], lo[2], lo[3]);
}

// ---------------- kernel 1: h = x@W^T via split-f16 HMMA; 32 rows/CTA ----------------
#define GX_HI 0
#define GX_LO 8704
#define GW_HI 17408
#define GW_LO 52224
#define GEMM_SMEM 87040
__global__ void __launch_bounds__(256, 2) k_gemm(const float* __restrict__ x,
                                                 const float* __restrict__ a) {
    extern __shared__ char smg[];
    const unsigned sb = smem_u32(smg);
    const int t = threadIdx.x, wid = t >> 5, lane = t & 31;
    const int row0 = blockIdx.x * 32;

    #pragma unroll
    for (int r = 0; r < 8; r++) {
        int id = t + r * 256;
        int d = id >> 4, q = id & 15;
        CP16(sb + GW_HI + d * 272 + q * 16, &g_w16hi[d * 128 + q * 8]);
        CP16(sb + GW_LO + d * 272 + q * 16, &g_w16lo[d * 128 + q * 8]);
    }
    asm volatile("cp.async.commit_group;" ::: "memory");

    {
        const int row = t >> 3, cq = (t & 7) * 16;
        const float* src = &x[(size_t)(row0 + row) * 128 + cq];
        float f[16];
        #pragma unroll
        for (int p = 0; p < 4; p++) {
            float4 v = *(const float4*)&src[p * 4];
            f[4*p] = v.x; f[4*p+1] = v.y; f[4*p+2] = v.z; f[4*p+3] = v.w;
        }
        unsigned hi[8], lo[8];
        #pragma unroll
        for (int p = 0; p < 8; p++) {
            unsigned uh = pk_f16x2(f[2*p], f[2*p+1]);
            float g0, g1; unpk_f16x2(uh, g0, g1);
            hi[p] = uh;
            lo[p] = pk_f16x2(f[2*p] - g0, f[2*p+1] - g1);
        }
        char* dh = smg + GX_HI + row * 272 + cq * 2;
        char* dl = smg + GX_LO + row * 272 + cq * 2;
        *(uint4*)dh       = make_uint4(hi[0], hi[1], hi[2], hi[3]);
        *(uint4*)(dh+16)  = make_uint4(hi[4], hi[5], hi[6], hi[7]);
        *(uint4*)dl       = make_uint4(lo[0], lo[1], lo[2], lo[3]);
        *(uint4*)(dl+16)  = make_uint4(lo[4], lo[5], lo[6], lo[7]);
    }
    asm volatile("cp.async.wait_group 0;" ::: "memory");
    __syncthreads();

    const int n0 = wid * 16;
    const unsigned aAh0 = sb + GX_HI + (unsigned)(lane & 15) * 272u + ((lane >> 4) & 1) * 16u;
    const unsigned aAh1 = aAh0 + 16u * 272u;
    const unsigned aAl0 = aAh0 + (GX_LO - GX_HI);
    const unsigned aAl1 = aAh1 + (GX_LO - GX_HI);
    const unsigned bB   = sb + GW_HI + (unsigned)(n0 + (lane & 7) + ((lane >> 4) & 1) * 8) * 272u
                        + ((lane >> 3) & 1) * 16u;
    const unsigned bBl  = bB + (GW_LO - GW_HI);

    float acc[2][2][4];
    #pragma unroll
    for (int mt = 0; mt < 2; mt++)
        #pragma unroll
        for (int nt = 0; nt < 2; nt++)
            #pragma unroll
            for (int k = 0; k < 4; k++) acc[mt][nt][k] = 0.f;

    #pragma unroll
    for (int ks = 0; ks < 8; ks++) {
        const unsigned off = (unsigned)ks * 32u;
        unsigned ah0[4], ah1[4], al0[4], al1[4];
        unsigned bh0, bh1, ch0, ch1, bl0, bl1, cl0, cl1;
        ldsm_x4(aAh0 + off, ah0[0], ah0[1], ah0[2], ah0[3]);
        ldsm_x4(aAh1 + off, ah1[0], ah1[1], ah1[2], ah1[3]);
        ldsm_x4(aAl0 + off, al0[0], al0[1], al0[2], al0[3]);
        ldsm_x4(aAl1 + off, al1[0], al1[1], al1[2], al1[3]);
        ldsm_x4(bB  + off, bh0, bh1, ch0, ch1);
        ldsm_x4(bBl + off, bl0, bl1, cl0, cl1);
        mma16816(acc[0][0], ah0, bh0, bh1);
        mma16816(acc[0][0], ah0, bl0, bl1);
        mma16816(acc[0][0], al0, bh0, bh1);
        mma16816(acc[0][1], ah0, ch0, ch1);
        mma16816(acc[0][1], ah0, cl0, cl1);
        mma16816(acc[0][1], al0, ch0, ch1);
        mma16816(acc[1][0], ah1, bh0, bh1);
        mma16816(acc[1][0], ah1, bl0, bl1);
        mma16816(acc[1][0], al1, bh0, bh1);
        mma16816(acc[1][1], ah1, ch0, ch1);
        mma16816(acc[1][1], ah1, cl0, cl1);
        mma16816(acc[1][1], al1, ch0, ch1);
    }

    __syncthreads();
    float* sm32 = (float*)smg;
    #pragma unroll
    for (int mt = 0; mt < 2; mt++)
        #pragma unroll
        for (int nt = 0; nt < 2; nt++) {
            const int r = mt * 16 + (lane >> 2);
            const int c = n0 + nt * 8 + 2 * (lane & 3);
            *(float2*)&sm32[r * 136 + c]       = make_float2(acc[mt][nt][0], acc[mt][nt][1]);
            *(float2*)&sm32[(r + 8) * 136 + c] = make_float2(acc[mt][nt][2], acc[mt][nt][3]);
        }
    __syncthreads();

    {
        const int bb = row0 >> 11, j0l = row0 & 2047;
        const int d = t >> 1, jh = t & 1;
        unsigned u[8];
        #pragma unroll
        for (int p = 0; p < 8; p++)
            u[p] = pk_f16x2(sm32[(jh * 16 + 2*p) * 136 + d], sm32[(jh * 16 + 2*p + 1) * 136 + d]);
        unsigned short* dst = &g_hp[(((size_t)bb * H_ + (d >> 5)) * HD_ + (d & 31)) * N_ + j0l + jh * 16];
        *(uint4*)dst      = make_uint4(u[0], u[1], u[2], u[3]);
        *(uint4*)(dst+8)  = make_uint4(u[4], u[5], u[6], u[7]);
    }

    {
        const int r = t >> 3, q = t & 7;
        const int head = q >> 1, part = q & 1;
        const float* hrow = &sm32[r * 136 + head * 32 + part * 16];
        const float* a1 = &a[head * 64 + part * 16];
        const float* a2 = a1 + 32;
        float p1 = 0.f, p2 = 0.f;
        #pragma unroll
        for (int dd = 0; dd < 16; dd++) {
            float hv = hrow[dd];
            p1 = fmaf(hv, a1[dd], p1);
            p2 = fmaf(hv, a2[dd], p2);
        }
        p1 += __shfl_xor_sync(0xffffffffu, p1, 1);
        p2 += __shfl_xor_sync(0xffffffffu, p2, 1);
        if (part == 0) {
            const int row = row0 + r;
            g_ei[row * H_ + head] = p1 * LOG2E;
            g_ej[row * H_ + head] = p2 * LOG2E;
        }
    }
}

// ---------------- kernel 2: pack adj (8 rows/warp, 2x uint4 out) ----------------
__global__ void k_pack(const int* __restrict__ adj) {
    const int wid = threadIdx.x >> 5, lane = threadIdx.x & 31;
    const int gw = blockIdx.x * 8 + wid;
    const int ip = gw >> 4, w4 = gw & 15;
    const int sub = lane >> 3, idx = lane & 7;
    const size_t base = (size_t)(8 * ip) * N_ + w4 * 128 + sub * 32 + idx * 4;
    unsigned aa[8];
    #pragma unroll
    for (int k = 0; k < 8; k++) {
        int4 v = *(const int4*)&adj[base + (size_t)k * N_];
        aa[k] = ((v.x != 0 ? 1u : 0u) | (v.y != 0 ? 2u : 0u)
               | (v.z != 0 ? 4u : 0u) | (v.w != 0 ? 8u : 0u)) << (idx * 4);
    }
    #pragma unroll
    for (int o = 1; o < 8; o <<= 1)
        #pragma unroll
        for (int k = 0; k < 8; k++)
            aa[k] |= __shfl_xor_sync(0xffffffffu, aa[k], o, 8);
    if (idx == 0) {
        *(uint4*)&g_adjw[(w4 * 4 + sub) * N_ + 8 * ip]     = make_uint4(aa[0], aa[1], aa[2], aa[3]);
        *(uint4*)&g_adjw[(w4 * 4 + sub) * N_ + 8 * ip + 4] = make_uint4(aa[4], aa[5], aa[6], aa[7]);
    }
}

// ---------------- kernel 3: fused scores-in-registers + HMMA, BI=64, 128 thr ----------------
#define OFF_H0   0          // 32 x 272
#define OFF_H1   8704
#define OFF_EJ   17408      // 2 x 512B
#define OFF_ADJ  18432      // 2 x 1024B
#define ATTN_SMEM 20480

__global__ void __launch_bounds__(128, 4) k_attn(float* __restrict__ out) {
    extern __shared__ char smc[];
    const unsigned sb = smem_u32(smc);
    const int t = threadIdx.x, wid = t >> 5, lane = t & 31;
    const int i0 = blockIdx.x * 64, hh = blockIdx.y, b = blockIdx.z;

    const int r0 = wid * 16 + (lane >> 2);     // local row (and r0+8)
    const float ei0 = g_ei[(b * N_ + i0 + r0) * H_ + hh];
    const float ei1 = g_ei[(b * N_ + i0 + r0 + 8) * H_ + hh];
    const unsigned short* hp = g_hp + ((size_t)((b * H_ + hh) * HD_)) * N_;

    const unsigned bRow = (unsigned)((lane & 7) + ((lane >> 4) & 1) * 8) * 272u
                        + ((lane >> 3) & 1) * 16u;
    const int c0 = 2 * (lane & 3);

    float dacc[4][4];
    #pragma unroll
    for (int nb = 0; nb < 4; nb++)
        #pragma unroll
        for (int k = 0; k < 4; k++) dacc[nb][k] = 0.f;
    float z0 = 0.f, z1 = 0.f;

    #define ISSUE_COPIES(tl, buf)                                                       \
    do {                                                                                \
        const int jj0 = (tl) * 128;                                                     \
        const unsigned offH_ = (buf) ? OFF_H1 : OFF_H0;                                 \
        _Pragma("unroll")                                                               \
        for (int r = 0; r < 4; r++) {                                                   \
            int id = t + r * 128;                                                       \
            int d = id >> 4, q = id & 15;                                               \
            CP16(sb + offH_ + d * 272 + q * 16, &hp[(size_t)d * N_ + jj0 + q * 8]);     \
        }                                                                               \
        CP4(sb + OFF_EJ + (buf) * 512 + t * 4, &g_ej[(b * N_ + jj0 + t) * H_ + hh]);    \
        if (t < 64) {                                                                   \
            int jwl = t >> 4, il4 = (t & 15) * 4;                                       \
            CP16(sb + OFF_ADJ + (buf) * 1024 + (jwl * 64 + il4) * 4,                    \
                 &g_adjw[((jj0 >> 5) + jwl) * N_ + i0 + il4]);                          \
        }                                                                               \
        asm volatile("cp.async.commit_group;" ::: "memory");                            \
    } while (0)

    ISSUE_COPIES(0, 0);

    for (int tile = 0; tile < 16; tile++) {
        const int cur = tile & 1;

        __syncthreads();   // prior compute on buffer cur^1 finished in ALL warps
        if (tile + 1 < 16) {
            ISSUE_COPIES(tile + 1, cur ^ 1);
            asm volatile("cp.async.wait_group 1;" ::: "memory");
        } else {
            asm volatile("cp.async.wait_group 0;" ::: "memory");
        }
        __syncthreads();   // stage(cur) visible to all

        // adj words for this tile (2 rows x 4 words)
        const unsigned* aw = (const unsigned*)(smc + OFF_ADJ + cur * 1024);
        unsigned wr0[4], wr1[4];
        #pragma unroll
        for (int jw = 0; jw < 4; jw++) {
            wr0[jw] = aw[jw * 64 + r0];
            wr1[jw] = aw[jw * 64 + r0 + 8];
        }
        const float* ejs = (const float*)(smc + OFF_EJ + cur * 512);
        const unsigned aB0 = sb + (cur ? OFF_H1 : OFF_H0) + bRow;
        const unsigned aB1 = aB0 + 16u * 272u;

        #pragma unroll
        for (int ks = 0; ks < 8; ks++) {
            const float* ejk = ejs + ks * 16;
            float2 eA = *(const float2*)&ejk[c0];
            float2 eB = *(const float2*)&ejk[c0 + 8];
            const unsigned wa = wr0[ks >> 1] >> ((ks & 1) * 16 + c0);
            const unsigned wb = wr1[ks >> 1] >> ((ks & 1) * 16 + c0);

            float s;
            s = ei0 + eA.x; s = fmaxf(s, 0.2f * s); float e00 = ex2f(s); e00 = (wa & 1u)   ? e00 : 0.f;
            s = ei0 + eA.y; s = fmaxf(s, 0.2f * s); float e01 = ex2f(s); e01 = (wa & 2u)   ? e01 : 0.f;
            s = ei0 + eB.x; s = fmaxf(s, 0.2f * s); float e08 = ex2f(s); e08 = (wa & 256u) ? e08 : 0.f;
            s = ei0 + eB.y; s = fmaxf(s, 0.2f * s); float e09 = ex2f(s); e09 = (wa & 512u) ? e09 : 0.f;
            s = ei1 + eA.x; s = fmaxf(s, 0.2f * s); float e10 = ex2f(s); e10 = (wb & 1u)   ? e10 : 0.f;
            s = ei1 + eA.y; s = fmaxf(s, 0.2f * s); float e11 = ex2f(s); e11 = (wb & 2u)   ? e11 : 0.f;
            s = ei1 + eB.x; s = fmaxf(s, 0.2f * s); float e18 = ex2f(s); e18 = (wb & 256u) ? e18 : 0.f;
            s = ei1 + eB.y; s = fmaxf(s, 0.2f * s); float e19 = ex2f(s); e19 = (wb & 512u) ? e19 : 0.f;

            z0 += (e00 + e01) + (e08 + e09);
            z1 += (e10 + e11) + (e18 + e19);

            unsigned afrag[4];
            afrag[0] = pk_f16x2(e00, e01);
            afrag[1] = pk_f16x2(e10, e11);
            afrag[2] = pk_f16x2(e08, e09);
            afrag[3] = pk_f16x2(e18, e19);

            const unsigned off = (unsigned)ks * 32u;
            unsigned b0, b1, c0r, c1r, f0, f1, g0, g1;
            ldsm_x4(aB0 + off, b0, b1, c0r, c1r);
            ldsm_x4(aB1 + off, f0, f1, g0, g1);
            mma16816(dacc[0], afrag, b0, b1);
            mma16816(dacc[1], afrag, c0r, c1r);
            mma16816(dacc[2], afrag, f0, f1);
            mma16816(dacc[3], afrag, g0, g1);
        }
    }

    // Z: reduce across the 4 lanes sharing a row (width-4 shuffle)
    z0 += __shfl_xor_sync(0xffffffffu, z0, 1, 4);
    z0 += __shfl_xor_sync(0xffffffffu, z0, 2, 4);
    z1 += __shfl_xor_sync(0xffffffffu, z1, 1, 4);
    z1 += __shfl_xor_sync(0xffffffffu, z1, 2, 4);
    const float zi0 = 1.0f / z0, zi1 = 1.0f / z1;

    const size_t row_g = (size_t)(b * N_) + i0 + r0;
    float* o0 = out + row_g * DIN + hh * HD_ + c0;
    float* o1 = o0 + 8 * DIN;
    #pragma unroll
    for (int nb = 0; nb < 4; nb++) {
        *(float2*)(o0 + nb * 8) = make_float2(dacc[nb][0] * zi0, dacc[nb][1] * zi0);
        *(float2*)(o1 + nb * 8) = make_float2(dacc[nb][2] * zi1, dacc[nb][3] * zi1);
    }
}

// ---------------- launch ----------------
extern "C" void kernel_launch(void* const* d_in, const int* in_sizes, int n_in,
                              void* d_out, int out_size) {
    const float* x   = (const float*)d_in[0];
    const int*   adj = (const int*)d_in[1];
    const float* W   = (const float*)d_in[2];
    const float* a   = (const float*)d_in[3];
    float*       out = (float*)d_out;

    cudaFuncSetAttribute(k_gemm, cudaFuncAttributeMaxDynamicSharedMemorySize, GEMM_SMEM);
    cudaFuncSetAttribute(k_attn, cudaFuncAttributeMaxDynamicSharedMemorySize, ATTN_SMEM);

    k_prep<<<8, 256>>>(W);
    k_gemm<<<B_ * N_ / 32, 256, GEMM_SMEM>>>(x, a);
    k_pack<<<512, 256>>>(adj);
    k_attn<<<dim3(N_ / 64, H_, B_), 128, ATTN_SMEM>>>(out);
}

// round 15
// speedup vs baseline: 1.2574x; 1.0007x over previous
#include <cuda_runtime.h>
#include <cuda_fp16.h>
#include <cstdint>

#define B_   4
#define N_   2048
#define DIN  128
#define H_   4
#define HD_  32
#define LOG2E 1.4426950408889634f

// ---------------- scratch (no allocs allowed) ----------------
__device__ float    g_ei[B_ * N_ * H_];      // pre-scaled by log2e
__device__ float    g_ej[B_ * N_ * H_];
__device__ unsigned g_adjw[(N_ / 32) * N_];  // [jw][i]  transposed bitmask
__device__ __align__(16) unsigned short g_hp[B_ * H_ * HD_ * N_];   // h f16 [b][h][d][j]
__device__ __align__(16) unsigned short g_w16hi[DIN * DIN];         // W split f16
__device__ __align__(16) unsigned short g_w16lo[DIN * DIN];

__device__ __forceinline__ float ex2f(float x) {
    float r; asm("ex2.approx.ftz.f32 %0, %1;" : "=f"(r) : "f"(x)); return r;
}
__device__ __forceinline__ unsigned pk_f16x2(float f0, float f1) {
    unsigned r;
    asm("cvt.rn.f16x2.f32 %0, %1, %2;" : "=r"(r) : "f"(f1), "f"(f0));
    return r;
}
__device__ __forceinline__ void unpk_f16x2(unsigned u, float& f0, float& f1) {
    asm("{ .reg .f16 l, h; mov.b32 {l, h}, %2; cvt.f32.f16 %0, l; cvt.f32.f16 %1, h; }"
        : "=f"(f0), "=f"(f1) : "r"(u));
}
__device__ __forceinline__ unsigned smem_u32(const void* p) {
    unsigned a;
    asm("{ .reg .u64 t; cvta.to.shared.u64 t, %1; cvt.u32.u64 %0, t; }" : "=r"(a) : "l"(p));
    return a;
}
#define CP16(dst, src) asm volatile("cp.async.cg.shared.global [%0], [%1], 16;" :: "r"(dst), "l"(src) : "memory")
#define CP4(dst, src)  asm volatile("cp.async.ca.shared.global [%0], [%1], 4;"  :: "r"(dst), "l"(src) : "memory")

__device__ __forceinline__ void ldsm_x4(unsigned addr, unsigned& a0, unsigned& a1,
                                        unsigned& a2, unsigned& a3) {
    asm volatile("ldmatrix.sync.aligned.m8n8.x4.shared.b16 {%0,%1,%2,%3}, [%4];"
                 : "=r"(a0), "=r"(a1), "=r"(a2), "=r"(a3) : "r"(addr));
}
__device__ __forceinline__ void mma16816(float* d, const unsigned* a, unsigned b0, unsigned b1) {
    asm volatile("mma.sync.aligned.m16n8k16.row.col.f32.f16.f16.f32 "
                 "{%0,%1,%2,%3}, {%4,%5,%6,%7}, {%8,%9}, {%0,%1,%2,%3};"
                 : "+f"(d[0]), "+f"(d[1]), "+f"(d[2]), "+f"(d[3])
                 : "r"(a[0]), "r"(a[1]), "r"(a[2]), "r"(a[3]), "r"(b0), "r"(b1));
}

// ---------------- kernel 0: split W -> f16 hi/lo planes ----------------
__global__ void k_prep(const float* __restrict__ W) {
    const int idx = (blockIdx.x * 256 + threadIdx.x) * 8;
    float4 v0 = *(const float4*)&W[idx];
    float4 v1 = *(const float4*)&W[idx + 4];
    float f[8] = {v0.x, v0.y, v0.z, v0.w, v1.x, v1.y, v1.z, v1.w};
    unsigned hi[4], lo[4];
    #pragma unroll
    for (int p = 0; p < 4; p++) {
        unsigned uh = pk_f16x2(f[2*p], f[2*p+1]);
        float g0, g1; unpk_f16x2(uh, g0, g1);
        hi[p] = uh;
        lo[p] = pk_f16x2(f[2*p] - g0, f[2*p+1] - g1);
    }
    *(uint4*)&g_w16hi[idx] = make_uint4(hi[0], hi[1], hi[2], hi[3]);
    *(uint4*)&g_w16lo[idx] = make_uint4(lo[0], lo[1], lo[2], lo[3]);
}

// ---------------- kernel 1: h = x@W^T via split-f16 HMMA; 32 rows/CTA ----------------
#define GX_HI 0
#define GX_LO 8704
#define GW_HI 17408
#define GW_LO 52224
#define GEMM_SMEM 87040
__global__ void __launch_bounds__(256, 2) k_gemm(const float* __restrict__ x,
                                                 const float* __restrict__ a) {
    extern __shared__ char smg[];
    const unsigned sb = smem_u32(smg);
    const int t = threadIdx.x, wid = t >> 5, lane = t & 31;
    const int row0 = blockIdx.x * 32;

    #pragma unroll
    for (int r = 0; r < 8; r++) {
        int id = t + r * 256;
        int d = id >> 4, q = id & 15;
        CP16(sb + GW_HI + d * 272 + q * 16, &g_w16hi[d * 128 + q * 8]);
        CP16(sb + GW_LO + d * 272 + q * 16, &g_w16lo[d * 128 + q * 8]);
    }
    asm volatile("cp.async.commit_group;" ::: "memory");

    {
        const int row = t >> 3, cq = (t & 7) * 16;
        const float* src = &x[(size_t)(row0 + row) * 128 + cq];
        float f[16];
        #pragma unroll
        for (int p = 0; p < 4; p++) {
            float4 v = *(const float4*)&src[p * 4];
            f[4*p] = v.x; f[4*p+1] = v.y; f[4*p+2] = v.z; f[4*p+3] = v.w;
        }
        unsigned hi[8], lo[8];
        #pragma unroll
        for (int p = 0; p < 8; p++) {
            unsigned uh = pk_f16x2(f[2*p], f[2*p+1]);
            float g0, g1; unpk_f16x2(uh, g0, g1);
            hi[p] = uh;
            lo[p] = pk_f16x2(f[2*p] - g0, f[2*p+1] - g1);
        }
        char* dh = smg + GX_HI + row * 272 + cq * 2;
        char* dl = smg + GX_LO + row * 272 + cq * 2;
        *(uint4*)dh       = make_uint4(hi[0], hi[1], hi[2], hi[3]);
        *(uint4*)(dh+16)  = make_uint4(hi[4], hi[5], hi[6], hi[7]);
        *(uint4*)dl       = make_uint4(lo[0], lo[1], lo[2], lo[3]);
        *(uint4*)(dl+16)  = make_uint4(lo[4], lo[5], lo[6], lo[7]);
    }
    asm volatile("cp.async.wait_group 0;" ::: "memory");
    __syncthreads();

    const int n0 = wid * 16;
    const unsigned aAh0 = sb + GX_HI + (unsigned)(lane & 15) * 272u + ((lane >> 4) & 1) * 16u;
    const unsigned aAh1 = aAh0 + 16u * 272u;
    const unsigned aAl0 = aAh0 + (GX_LO - GX_HI);
    const unsigned aAl1 = aAh1 + (GX_LO - GX_HI);
    const unsigned bB   = sb + GW_HI + (unsigned)(n0 + (lane & 7) + ((lane >> 4) & 1) * 8) * 272u
                        + ((lane >> 3) & 1) * 16u;
    const unsigned bBl  = bB + (GW_LO - GW_HI);

    float acc[2][2][4];
    #pragma unroll
    for (int mt = 0; mt < 2; mt++)
        #pragma unroll
        for (int nt = 0; nt < 2; nt++)
            #pragma unroll
            for (int k = 0; k < 4; k++) acc[mt][nt][k] = 0.f;

    #pragma unroll
    for (int ks = 0; ks < 8; ks++) {
        const unsigned off = (unsigned)ks * 32u;
        unsigned ah0[4], ah1[4], al0[4], al1[4];
        unsigned bh0, bh1, ch0, ch1, bl0, bl1, cl0, cl1;
        ldsm_x4(aAh0 + off, ah0[0], ah0[1], ah0[2], ah0[3]);
        ldsm_x4(aAh1 + off, ah1[0], ah1[1], ah1[2], ah1[3]);
        ldsm_x4(aAl0 + off, al0[0], al0[1], al0[2], al0[3]);
        ldsm_x4(aAl1 + off, al1[0], al1[1], al1[2], al1[3]);
        ldsm_x4(bB  + off, bh0, bh1, ch0, ch1);
        ldsm_x4(bBl + off, bl0, bl1, cl0, cl1);
        mma16816(acc[0][0], ah0, bh0, bh1);
        mma16816(acc[0][0], ah0, bl0, bl1);
        mma16816(acc[0][0], al0, bh0, bh1);
        mma16816(acc[0][1], ah0, ch0, ch1);
        mma16816(acc[0][1], ah0, cl0, cl1);
        mma16816(acc[0][1], al0, ch0, ch1);
        mma16816(acc[1][0], ah1, bh0, bh1);
        mma16816(acc[1][0], ah1, bl0, bl1);
        mma16816(acc[1][0], al1, bh0, bh1);
        mma16816(acc[1][1], ah1, ch0, ch1);
        mma16816(acc[1][1], ah1, cl0, cl1);
        mma16816(acc[1][1], al1, ch0, ch1);
    }

    __syncthreads();
    float* sm32 = (float*)smg;
    #pragma unroll
    for (int mt = 0; mt < 2; mt++)
        #pragma unroll
        for (int nt = 0; nt < 2; nt++) {
            const int r = mt * 16 + (lane >> 2);
            const int c = n0 + nt * 8 + 2 * (lane & 3);
            *(float2*)&sm32[r * 136 + c]       = make_float2(acc[mt][nt][0], acc[mt][nt][1]);
            *(float2*)&sm32[(r + 8) * 136 + c] = make_float2(acc[mt][nt][2], acc[mt][nt][3]);
        }
    __syncthreads();

    {
        const int bb = row0 >> 11, j0l = row0 & 2047;
        const int d = t >> 1, jh = t & 1;
        unsigned u[8];
        #pragma unroll
        for (int p = 0; p < 8; p++)
            u[p] = pk_f16x2(sm32[(jh * 16 + 2*p) * 136 + d], sm32[(jh * 16 + 2*p + 1) * 136 + d]);
        unsigned short* dst = &g_hp[(((size_t)bb * H_ + (d >> 5)) * HD_ + (d & 31)) * N_ + j0l + jh * 16];
        *(uint4*)dst      = make_uint4(u[0], u[1], u[2], u[3]);
        *(uint4*)(dst+8)  = make_uint4(u[4], u[5], u[6], u[7]);
    }

    {
        const int r = t >> 3, q = t & 7;
        const int head = q >> 1, part = q & 1;
        const float* hrow = &sm32[r * 136 + head * 32 + part * 16];
        const float* a1 = &a[head * 64 + part * 16];
        const float* a2 = a1 + 32;
        float p1 = 0.f, p2 = 0.f;
        #pragma unroll
        for (int dd = 0; dd < 16; dd++) {
            float hv = hrow[dd];
            p1 = fmaf(hv, a1[dd], p1);
            p2 = fmaf(hv, a2[dd], p2);
        }
        p1 += __shfl_xor_sync(0xffffffffu, p1, 1);
        p2 += __shfl_xor_sync(0xffffffffu, p2, 1);
        if (part == 0) {
            const int row = row0 + r;
            g_ei[row * H_ + head] = p1 * LOG2E;
            g_ej[row * H_ + head] = p2 * LOG2E;
        }
    }
}

// ---------------- kernel 2: pack adj (8 rows/warp, 2x uint4 out) ----------------
__global__ void k_pack(const int* __restrict__ adj) {
    const int wid = threadIdx.x >> 5, lane = threadIdx.x & 31;
    const int gw = blockIdx.x * 8 + wid;
    const int ip = gw >> 4, w4 = gw & 15;
    const int sub = lane >> 3, idx = lane & 7;
    const size_t base = (size_t)(8 * ip) * N_ + w4 * 128 + sub * 32 + idx * 4;
    unsigned aa[8];
    #pragma unroll
    for (int k = 0; k < 8; k++) {
        int4 v = *(const int4*)&adj[base + (size_t)k * N_];
        aa[k] = ((v.x != 0 ? 1u : 0u) | (v.y != 0 ? 2u : 0u)
               | (v.z != 0 ? 4u : 0u) | (v.w != 0 ? 8u : 0u)) << (idx * 4);
    }
    #pragma unroll
    for (int o = 1; o < 8; o <<= 1)
        #pragma unroll
        for (int k = 0; k < 8; k++)
            aa[k] |= __shfl_xor_sync(0xffffffffu, aa[k], o, 8);
    if (idx == 0) {
        *(uint4*)&g_adjw[(w4 * 4 + sub) * N_ + 8 * ip]     = make_uint4(aa[0], aa[1], aa[2], aa[3]);
        *(uint4*)&g_adjw[(w4 * 4 + sub) * N_ + 8 * ip + 4] = make_uint4(aa[4], aa[5], aa[6], aa[7]);
    }
}

// ---------------- kernel 3: fused scores-in-registers + HMMA, BI=64, 128 thr ----------------
#define OFF_H0   0          // 32 x 272
#define OFF_H1   8704
#define OFF_EJ   17408      // 2 x 512B
#define OFF_ADJ  18432      // 2 x 1024B
#define ATTN_SMEM 20480

__global__ void __launch_bounds__(128, 4) k_attn(float* __restrict__ out) {
    extern __shared__ char smc[];
    const unsigned sb = smem_u32(smc);
    const int t = threadIdx.x, wid = t >> 5, lane = t & 31;
    const int i0 = blockIdx.x * 64, hh = blockIdx.y, b = blockIdx.z;

    const int r0 = wid * 16 + (lane >> 2);     // local row (and r0+8)
    const float ei0 = g_ei[(b * N_ + i0 + r0) * H_ + hh];
    const float ei1 = g_ei[(b * N_ + i0 + r0 + 8) * H_ + hh];
    const unsigned short* hp = g_hp + ((size_t)((b * H_ + hh) * HD_)) * N_;

    const unsigned bRow = (unsigned)((lane & 7) + ((lane >> 4) & 1) * 8) * 272u
                        + ((lane >> 3) & 1) * 16u;
    const int c0 = 2 * (lane & 3);

    float dacc[4][4];
    #pragma unroll
    for (int nb = 0; nb < 4; nb++)
        #pragma unroll
        for (int k = 0; k < 4; k++) dacc[nb][k] = 0.f;
    float z0 = 0.f, z1 = 0.f;

    #define ISSUE_COPIES(tl, buf)                                                       \
    do {                                                                                \
        const int jj0 = (tl) * 128;                                                     \
        const unsigned offH_ = (buf) ? OFF_H1 : OFF_H0;                                 \
        _Pragma("unroll")                                                               \
        for (int r = 0; r < 4; r++) {                                                   \
            int id = t + r * 128;                                                       \
            int d = id >> 4, q = id & 15;                                               \
            CP16(sb + offH_ + d * 272 + q * 16, &hp[(size_t)d * N_ + jj0 + q * 8]);     \
        }                                                                               \
        CP4(sb + OFF_EJ + (buf) * 512 + t * 4, &g_ej[(b * N_ + jj0 + t) * H_ + hh]);    \
        if (t < 64) {                                                                   \
            int jwl = t >> 4, il4 = (t & 15) * 4;                                       \
            CP16(sb + OFF_ADJ + (buf) * 1024 + (jwl * 64 + il4) * 4,                    \
                 &g_adjw[((jj0 >> 5) + jwl) * N_ + i0 + il4]);                          \
        }                                                                               \
        asm volatile("cp.async.commit_group;" ::: "memory");                            \
    } while (0)

    ISSUE_COPIES(0, 0);

    for (int tile = 0; tile < 16; tile++) {
        const int cur = tile & 1;

        __syncthreads();   // prior compute on buffer cur^1 finished in ALL warps
        if (tile + 1 < 16) {
            ISSUE_COPIES(tile + 1, cur ^ 1);
            asm volatile("cp.async.wait_group 1;" ::: "memory");
        } else {
            asm volatile("cp.async.wait_group 0;" ::: "memory");
        }
        __syncthreads();   // stage(cur) visible to all

        // adj words for this tile (2 rows x 4 words)
        const unsigned* aw = (const unsigned*)(smc + OFF_ADJ + cur * 1024);
        unsigned wr0[4], wr1[4];
        #pragma unroll
        for (int jw = 0; jw < 4; jw++) {
            wr0[jw] = aw[jw * 64 + r0];
            wr1[jw] = aw[jw * 64 + r0 + 8];
        }
        const float* ejs = (const float*)(smc + OFF_EJ + cur * 512);
        const unsigned aB0 = sb + (cur ? OFF_H1 : OFF_H0) + bRow;
        const unsigned aB1 = aB0 + 16u * 272u;

        #pragma unroll
        for (int ks = 0; ks < 8; ks++) {
            const float* ejk = ejs + ks * 16;
            float2 eA = *(const float2*)&ejk[c0];
            float2 eB = *(const float2*)&ejk[c0 + 8];
            const unsigned wa = wr0[ks >> 1] >> ((ks & 1) * 16 + c0);
            const unsigned wb = wr1[ks >> 1] >> ((ks & 1) * 16 + c0);

            float s;
            s = ei0 + eA.x; s = fmaxf(s, 0.2f * s); float e00 = ex2f(s); e00 = (wa & 1u)   ? e00 : 0.f;
            s = ei0 + eA.y; s = fmaxf(s, 0.2f * s); float e01 = ex2f(s); e01 = (wa & 2u)   ? e01 : 0.f;
            s = ei0 + eB.x; s = fmaxf(s, 0.2f * s); float e08 = ex2f(s); e08 = (wa & 256u) ? e08 : 0.f;
            s = ei0 + eB.y; s = fmaxf(s, 0.2f * s); float e09 = ex2f(s); e09 = (wa & 512u) ? e09 : 0.f;
            s = ei1 + eA.x; s = fmaxf(s, 0.2f * s); float e10 = ex2f(s); e10 = (wb & 1u)   ? e10 : 0.f;
            s = ei1 + eA.y; s = fmaxf(s, 0.2f * s); float e11 = ex2f(s); e11 = (wb & 2u)   ? e11 : 0.f;
            s = ei1 + eB.x; s = fmaxf(s, 0.2f * s); float e18 = ex2f(s); e18 = (wb & 256u) ? e18 : 0.f;
            s = ei1 + eB.y; s = fmaxf(s, 0.2f * s); float e19 = ex2f(s); e19 = (wb & 512u) ? e19 : 0.f;

            z0 += (e00 + e01) + (e08 + e09);
            z1 += (e10 + e11) + (e18 + e19);

            unsigned afrag[4];
            afrag[0] = pk_f16x2(e00, e01);
            afrag[1] = pk_f16x2(e10, e11);
            afrag[2] = pk_f16x2(e08, e09);
            afrag[3] = pk_f16x2(e18, e19);

            const unsigned off = (unsigned)ks * 32u;
            unsigned b0, b1, c0r, c1r, f0, f1, g0, g1;
            ldsm_x4(aB0 + off, b0, b1, c0r, c1r);
            ldsm_x4(aB1 + off, f0, f1, g0, g1);
            mma16816(dacc[0], afrag, b0, b1);
            mma16816(dacc[1], afrag, c0r, c1r);
            mma16816(dacc[2], afrag, f0, f1);
            mma16816(dacc[3], afrag, g0, g1);
        }
    }

    // Z: reduce across the 4 lanes sharing a row (width-4 shuffle)
    z0 += __shfl_xor_sync(0xffffffffu, z0, 1, 4);
    z0 += __shfl_xor_sync(0xffffffffu, z0, 2, 4);
    z1 += __shfl_xor_sync(0xffffffffu, z1, 1, 4);
    z1 += __shfl_xor_sync(0xffffffffu, z1, 2, 4);
    const float zi0 = 1.0f / z0, zi1 = 1.0f / z1;

    const size_t row_g = (size_t)(b * N_) + i0 + r0;
    float* o0 = out + row_g * DIN + hh * HD_ + c0;
    float* o1 = o0 + 8 * DIN;
    #pragma unroll
    for (int nb = 0; nb < 4; nb++) {
        *(float2*)(o0 + nb * 8) = make_float2(dacc[nb][0] * zi0, dacc[nb][1] * zi0);
        *(float2*)(o1 + nb * 8) = make_float2(dacc[nb][2] * zi1, dacc[nb][3] * zi1);
    }
}

// ---------------- launch ----------------
extern "C" void kernel_launch(void* const* d_in, const int* in_sizes, int n_in,
                              void* d_out, int out_size) {
    const float* x   = (const float*)d_in[0];
    const int*   adj = (const int*)d_in[1];
    const float* W   = (const float*)d_in[2];
    const float* a   = (const float*)d_in[3];
    float*       out = (float*)d_out;

    cudaFuncSetAttribute(k_gemm, cudaFuncAttributeMaxDynamicSharedMemorySize, GEMM_SMEM);
    cudaFuncSetAttribute(k_attn, cudaFuncAttributeMaxDynamicSharedMemorySize, ATTN_SMEM);

    k_prep<<<8, 256>>>(W);
    k_gemm<<<B_ * N_ / 32, 256, GEMM_SMEM>>>(x, a);
    k_pack<<<512, 256>>>(adj);
    k_attn<<<dim3(N_ / 64, H_, B_), 128, ATTN_SMEM>>>(out);
}